// round 1
// baseline (speedup 1.0000x reference)
#include <cuda_runtime.h>

#define BB   32
#define CC   128
#define HH   56
#define WW   56
#define HWS  (HH*WW)          // 3136
#define NPIX (BB*HWS)         // 100352
#define NELT (NPIX*CC)        // 12845056
#define SBLK 1024
#define CONV_SMEM ((CC*289 + 4*58*32) * 4)   // 177664 bytes

// ----------------------------- scratch (device globals: no runtime allocs) --
__device__ signed char g_xq[NELT];          // x quantized, NHWC int8
__device__ signed char g_aq[NELT];          // a1 quantized, NHWC int8
__device__ float       g_y[NELT];           // conv output (reused layer1/2), NHWC
__device__ signed char g_w1q[CC*9*CC];      // [co][tap][ci] int8
__device__ signed char g_w2q[CC*9*CC];
__device__ unsigned    g_sx_bits;           // atomicMax target (abs-max bits of x)
__device__ float       g_sw1, g_sw2, g_sa1; // scales (incl +1e-12)
__device__ float       g_bnA[2*CC], g_bnB[2*CC]; // folded BN: y*A + B
__device__ double      g_psum[SBLK*CC], g_psum2[SBLK*CC];
__device__ float       g_pmin[SBLK*CC], g_pmax[SBLK*CC];

// ----------------------------------------------------------------- helpers --
__global__ void k_zero() { g_sx_bits = 0u; }

__global__ void k_absmax_x(const float* __restrict__ x) {
    float m = 0.f;
    for (int i = blockIdx.x*blockDim.x + threadIdx.x; i < NELT; i += gridDim.x*blockDim.x)
        m = fmaxf(m, fabsf(x[i]));
    #pragma unroll
    for (int o = 16; o; o >>= 1) m = fmaxf(m, __shfl_xor_sync(0xffffffffu, m, o));
    __shared__ float s[32];
    int w = threadIdx.x >> 5, l = threadIdx.x & 31;
    if (l == 0) s[w] = m;
    __syncthreads();
    if (w == 0) {
        m = (l < (blockDim.x >> 5)) ? s[l] : 0.f;
        #pragma unroll
        for (int o = 16; o; o >>= 1) m = fmaxf(m, __shfl_xor_sync(0xffffffffu, m, o));
        if (l == 0) atomicMax(&g_sx_bits, __float_as_uint(m));  // deterministic
    }
}

__global__ void k_absmax_w(const float* __restrict__ w1, const float* __restrict__ w2) {
    const float* w = blockIdx.x ? w2 : w1;
    float m = 0.f;
    for (int i = threadIdx.x; i < CC*CC*9; i += blockDim.x) m = fmaxf(m, fabsf(w[i]));
    #pragma unroll
    for (int o = 16; o; o >>= 1) m = fmaxf(m, __shfl_xor_sync(0xffffffffu, m, o));
    __shared__ float s[32];
    int wi = threadIdx.x >> 5, l = threadIdx.x & 31;
    if (l == 0) s[wi] = m;
    __syncthreads();
    if (wi == 0) {
        m = (l < (blockDim.x >> 5)) ? s[l] : 0.f;
        #pragma unroll
        for (int o = 16; o; o >>= 1) m = fmaxf(m, __shfl_xor_sync(0xffffffffu, m, o));
        if (l == 0) { float sc = m + 1e-12f; if (blockIdx.x) g_sw2 = sc; else g_sw1 = sc; }
    }
}

// NCHW fp32 -> NHWC int8 via smem tile (coalesced both sides)
__global__ void k_quant_x(const float* __restrict__ x) {
    __shared__ signed char t8[CC][120];
    int n = blockIdx.y, hw0 = blockIdx.x * 112;
    float qs = 127.f / (__uint_as_float(g_sx_bits) + 1e-12f);
    for (int i = threadIdx.x; i < CC*112; i += blockDim.x) {
        int c = i / 112, p = i % 112;
        float v = x[(size_t)(n*CC + c)*HWS + hw0 + p];
        int qi = __float2int_rn(v * qs);
        qi = max(-127, min(127, qi));
        t8[c][p] = (signed char)qi;
    }
    __syncthreads();
    for (int i = threadIdx.x; i < 112*32; i += blockDim.x) {
        int p = i / 32, cq = i % 32;
        char4 v = make_char4(t8[cq*4][p], t8[cq*4+1][p], t8[cq*4+2][p], t8[cq*4+3][p]);
        *reinterpret_cast<char4*>(&g_xq[(size_t)(n*HWS + hw0 + p)*CC + cq*4]) = v;
    }
}

// OIHW fp32 -> [co][tap][ci] int8 for both weight tensors
__global__ void k_quant_w(const float* __restrict__ w1, const float* __restrict__ w2) {
    int t = blockIdx.y;
    const float* w = t ? w2 : w1;
    signed char* o = t ? g_w2q : g_w1q;
    float q = 127.f / (t ? g_sw2 : g_sw1);
    for (int i = blockIdx.x*blockDim.x + threadIdx.x; i < CC*9*CC; i += gridDim.x*blockDim.x) {
        int co = i / (9*CC), r = i % (9*CC), tap = r / CC, ci = r % CC;
        float v = w[(co*CC + ci)*9 + tap];
        int qi = __float2int_rn(v * q);
        qi = max(-127, min(127, qi));
        o[i] = (signed char)qi;
    }
}

// 3x3 conv, int8 dp4a, NHWC. Block: 512 thr, 2 output rows x 56 cols x 128 co.
__global__ void __launch_bounds__(512, 1)
k_conv(int layer) {
    extern __shared__ int sm[];
    int* w_s = sm;              // [128][289]  (pad 289 -> conflict-free co loads)
    int* x_s = sm + CC*289;     // [4][58][32] int-packed int8 NHWC halo tile

    const signed char* act = layer ? g_aq  : g_xq;
    const signed char* wq  = layer ? g_w2q : g_w1q;

    int tid = threadIdx.x;
    int n  = blockIdx.y;
    int h0 = blockIdx.x * 2;

    const int* wg = reinterpret_cast<const int*>(wq);
    for (int i = tid; i < CC*288; i += 512) {
        int co = i / 288, k = i % 288;
        w_s[co*289 + k] = wg[i];
    }
    const int* xg = reinterpret_cast<const int*>(act);
    for (int i = tid; i < 4*58*32; i += 512) {
        int r4 = i / (58*32), rem = i % (58*32), col = rem / 32, k = rem % 32;
        int gr = h0 - 1 + r4, gc = col - 1;
        int v = 0;
        if (gr >= 0 && gr < HH && gc >= 0 && gc < WW)
            v = xg[((n*HWS) + gr*WW + gc)*32 + k];
        x_s[i] = v;
    }
    __syncthreads();

    int lane = tid & 31, pg = tid >> 5;
    int orow = pg >> 3;             // 0..1
    int ocol = (pg & 7) * 7;        // 0,7,...,49

    int acc[4][7];
    #pragma unroll
    for (int i = 0; i < 4; i++)
        #pragma unroll
        for (int j = 0; j < 7; j++) acc[i][j] = 0;

    #pragma unroll
    for (int dr = 0; dr < 3; dr++) {
        #pragma unroll
        for (int dc = 0; dc < 3; dc++) {
            int tap = dr*3 + dc;
            const int* xb = x_s + ((orow + dr)*58 + (ocol + dc))*32;
            const int* wb = w_s + lane*289 + tap*32;
            #pragma unroll 4
            for (int k = 0; k < 32; k++) {
                int w0 = wb[k];
                int w1 = wb[32*289 + k];
                int w2 = wb[64*289 + k];
                int w3 = wb[96*289 + k];
                #pragma unroll
                for (int j = 0; j < 7; j++) {
                    int xv = xb[j*32 + k];   // warp-broadcast, conflict-free
                    acc[0][j] = __dp4a(xv, w0, acc[0][j]);
                    acc[1][j] = __dp4a(xv, w1, acc[1][j]);
                    acc[2][j] = __dp4a(xv, w2, acc[2][j]);
                    acc[3][j] = __dp4a(xv, w3, acc[3][j]);
                }
            }
        }
    }

    float sact  = layer ? g_sa1 : (__uint_as_float(g_sx_bits) + 1e-12f);
    float sw    = layer ? g_sw2 : g_sw1;
    float scale = sact * sw * (1.f / 16129.f);   // /(127*127)
    int oh = h0 + orow;
    #pragma unroll
    for (int j = 0; j < 7; j++) {
        size_t base = ((size_t)(n*HWS) + oh*WW + ocol + j) * CC;
        #pragma unroll
        for (int i = 0; i < 4; i++)
            g_y[base + lane + 32*i] = (float)acc[i][j] * scale;
    }
}

// deterministic per-block partial BN stats (double sum/sumsq + min/max) over NHWC
__global__ void k_bnstats() {
    int tid = threadIdx.x;
    int c = tid & 127, half = tid >> 7;
    double s = 0.0, s2 = 0.0;
    float mn = 3.4e38f, mx = -3.4e38f;
    for (int pix = blockIdx.x*2 + half; pix < NPIX; pix += gridDim.x*2) {
        float v = g_y[(size_t)pix*CC + c];
        s += (double)v;
        s2 = fma((double)v, (double)v, s2);
        mn = fminf(mn, v); mx = fmaxf(mx, v);
    }
    __shared__ double ss[CC], ss2[CC];
    __shared__ float  smn[CC], smx[CC];
    if (half) { ss[c] = s; ss2[c] = s2; smn[c] = mn; smx[c] = mx; }
    __syncthreads();
    if (!half) {
        s += ss[c]; s2 += ss2[c];
        mn = fminf(mn, smn[c]); mx = fmaxf(mx, smx[c]);
        int o = blockIdx.x*CC + c;
        g_psum[o] = s; g_psum2[o] = s2; g_pmin[o] = mn; g_pmax[o] = mx;
    }
}

// final reduce: mean/rstd per channel; activation scale via channel min/max trick
__global__ void k_bnfin(const float* __restrict__ gamma, const float* __restrict__ beta,
                        int layer, int doAct) {
    int tid = threadIdx.x;
    int c = tid & 127, q = tid >> 7;          // 512 threads: 4-way split over blocks
    double s = 0.0, s2 = 0.0;
    float mn = 3.4e38f, mx = -3.4e38f;
    for (int b = q; b < SBLK; b += 4) {
        int o = b*CC + c;
        s += g_psum[o]; s2 += g_psum2[o];
        mn = fminf(mn, g_pmin[o]); mx = fmaxf(mx, g_pmax[o]);
    }
    __shared__ double ss[512], ss2[512];
    __shared__ float  smn[512], smx[512];
    __shared__ float  actmax[CC];
    ss[tid] = s; ss2[tid] = s2; smn[tid] = mn; smx[tid] = mx;
    __syncthreads();
    if (q == 0) {
        #pragma unroll
        for (int k = 1; k < 4; k++) {
            s += ss[k*128 + c]; s2 += ss2[k*128 + c];
            mn = fminf(mn, smn[k*128 + c]); mx = fmaxf(mx, smx[k*128 + c]);
        }
        double mean = s / (double)NPIX;
        double var  = s2 / (double)NPIX - mean*mean;
        float rstd = (float)(1.0 / sqrt(var + 1e-5));
        float A  = gamma[c] * rstd;
        float Bc = beta[c] - (float)mean * A;
        g_bnA[layer*CC + c] = A;
        g_bnB[layer*CC + c] = Bc;
        // max|relu(bn(y))| per channel from y extremes (bn affine monotone per channel)
        actmax[c] = fmaxf(fmaxf(mx*A + Bc, 0.f), fmaxf(mn*A + Bc, 0.f));
    }
    __syncthreads();
    if (doAct && tid == 0) {
        float m = 0.f;
        for (int k = 0; k < CC; k++) m = fmaxf(m, actmax[k]);
        g_sa1 = m + 1e-12f;
    }
}

// bn1 + relu + quantize -> a1 int8 (NHWC, vectorized x4)
__global__ void k_bnq() {
    int i4 = blockIdx.x*blockDim.x + threadIdx.x;
    if (i4 >= NELT/4) return;
    float qa = 127.f / g_sa1;
    float4 v = reinterpret_cast<const float4*>(g_y)[i4];
    int cb = (i4 & 31) * 4;
    float t0 = fmaxf(v.x*g_bnA[cb+0] + g_bnB[cb+0], 0.f);
    float t1 = fmaxf(v.y*g_bnA[cb+1] + g_bnB[cb+1], 0.f);
    float t2 = fmaxf(v.z*g_bnA[cb+2] + g_bnB[cb+2], 0.f);
    float t3 = fmaxf(v.w*g_bnA[cb+3] + g_bnB[cb+3], 0.f);
    char4 o;
    o.x = (signed char)max(-127, min(127, __float2int_rn(t0*qa)));
    o.y = (signed char)max(-127, min(127, __float2int_rn(t1*qa)));
    o.z = (signed char)max(-127, min(127, __float2int_rn(t2*qa)));
    o.w = (signed char)max(-127, min(127, __float2int_rn(t3*qa)));
    reinterpret_cast<char4*>(g_aq)[i4] = o;
}

// bn2 + identity add + relu, NHWC -> NCHW via smem transpose (all sides coalesced)
__global__ void k_final(const float* __restrict__ x, float* __restrict__ out) {
    __shared__ float t[CC][57];
    int n = blockIdx.y, row = blockIdx.x;
    int hw0 = row * WW;
    for (int i = threadIdx.x; i < WW*CC; i += blockDim.x) {
        int c = i & 127, p = i >> 7;
        t[c][p] = g_y[(size_t)(n*HWS + hw0 + p)*CC + c];
    }
    __syncthreads();
    for (int i = threadIdx.x; i < CC*WW; i += blockDim.x) {
        int c = i / WW, p = i % WW;
        size_t gi = (size_t)(n*CC + c)*HWS + hw0 + p;
        float v = t[c][p]*g_bnA[CC + c] + g_bnB[CC + c] + x[gi];
        out[gi] = fmaxf(v, 0.f);
    }
}

// ---------------------------------------------------------------- launcher --
extern "C" void kernel_launch(void* const* d_in, const int* in_sizes, int n_in,
                              void* d_out, int out_size) {
    const float* x      = (const float*)d_in[0];
    const float* w1     = (const float*)d_in[1];
    const float* gamma1 = (const float*)d_in[2];
    const float* beta1  = (const float*)d_in[3];
    const float* w2     = (const float*)d_in[4];
    const float* gamma2 = (const float*)d_in[5];
    const float* beta2  = (const float*)d_in[6];
    float* out = (float*)d_out;
    (void)in_sizes; (void)n_in; (void)out_size;

    cudaFuncSetAttribute(k_conv, cudaFuncAttributeMaxDynamicSharedMemorySize, CONV_SMEM);

    k_zero<<<1, 1>>>();
    k_absmax_x<<<1024, 256>>>(x);
    k_absmax_w<<<2, 1024>>>(w1, w2);
    k_quant_x<<<dim3(28, BB), 256>>>(x);
    k_quant_w<<<dim3(64, 2), 256>>>(w1, w2);

    k_conv<<<dim3(28, BB), 512, CONV_SMEM>>>(0);
    k_bnstats<<<SBLK, 256>>>();
    k_bnfin<<<1, 512>>>(gamma1, beta1, 0, 1);
    k_bnq<<<(NELT/4 + 255)/256, 256>>>();

    k_conv<<<dim3(28, BB), 512, CONV_SMEM>>>(1);
    k_bnstats<<<SBLK, 256>>>();
    k_bnfin<<<1, 512>>>(gamma2, beta2, 1, 0);
    k_final<<<dim3(HH, BB), 256>>>(x, out);
}

// round 7
// speedup vs baseline: 1.0484x; 1.0484x over previous
#include <cuda_runtime.h>
#include <cstdint>

#define BB   32
#define CC   128
#define HH   56
#define WW   56
#define HWS  (HH*WW)          // 3136
#define NPIX (BB*HWS)         // 100352
#define NELT (NPIX*CC)        // 12845056
#define SBLK 1024

// padded spatial layout: 58x58 per image (zero ring) + guard rows front/back
#define HP    58
#define PIMG  (HP*HP)         // 3364
#define GUARD 192             // guard rows (128 ch each) for tap shifts / tile overflow
#define NTILE 27              // ceil(3364/128)
#define TAPB  16384           // one 128(pix|co) x 128(ci) int8 tile
#define CONV_SMEM (4*TAPB)    // 2 stages x (A+B) = 64KB

// ----------------------------- scratch (device globals: no runtime allocs) --
__device__ signed char g_apad[((size_t)GUARD + (size_t)BB*PIMG + GUARD) * CC]; // padded acts int8
__device__ float       g_y[NELT];           // conv output, compact NHWC fp32
__device__ signed char g_w1q[9*CC*CC];      // [tap][co][ci] int8
__device__ signed char g_w2q[9*CC*CC];
__device__ unsigned    g_sx_bits;
__device__ float       g_sw1, g_sw2, g_sa1;
__device__ float       g_bnA[2*CC], g_bnB[2*CC];
__device__ double      g_psum[SBLK*CC], g_psum2[SBLK*CC];
__device__ float       g_pmin[SBLK*CC], g_pmax[SBLK*CC];

// --------------------------------------------------------------- PTX glue --
__device__ __forceinline__ uint32_t smem_u32(const void* p) {
    uint32_t a;
    asm("{ .reg .u64 t; cvta.to.shared.u64 t, %1; cvt.u32.u64 %0, t; }" : "=r"(a) : "l"(p));
    return a;
}
__device__ __forceinline__ void cpasync16(uint32_t dst, const void* src) {
    asm volatile("cp.async.cg.shared.global [%0], [%1], 16;" :: "r"(dst), "l"(src));
}
#define CP_COMMIT() asm volatile("cp.async.commit_group;" ::: "memory")
#define CP_WAIT0()  asm volatile("cp.async.wait_group 0;" ::: "memory")
#define CP_WAIT1()  asm volatile("cp.async.wait_group 1;" ::: "memory")

__device__ __forceinline__ void ldsm_x4(uint32_t& r0, uint32_t& r1, uint32_t& r2, uint32_t& r3,
                                        uint32_t addr) {
    asm volatile("ldmatrix.sync.aligned.m8n8.x4.shared.b16 {%0,%1,%2,%3}, [%4];"
                 : "=r"(r0), "=r"(r1), "=r"(r2), "=r"(r3) : "r"(addr));
}
__device__ __forceinline__ void mma_s8(int* c, const uint32_t* a, const uint32_t* b) {
    asm volatile("mma.sync.aligned.m16n8k32.row.col.s32.s8.s8.s32 "
                 "{%0,%1,%2,%3}, {%4,%5,%6,%7}, {%8,%9}, {%0,%1,%2,%3};"
                 : "+r"(c[0]), "+r"(c[1]), "+r"(c[2]), "+r"(c[3])
                 : "r"(a[0]), "r"(a[1]), "r"(a[2]), "r"(a[3]), "r"(b[0]), "r"(b[1]));
}

// ----------------------------------------------------------------- helpers --
__global__ void k_zero() { g_sx_bits = 0u; }

__global__ void k_absmax_x(const float* __restrict__ x) {
    float m = 0.f;
    for (int i = blockIdx.x*blockDim.x + threadIdx.x; i < NELT; i += gridDim.x*blockDim.x)
        m = fmaxf(m, fabsf(x[i]));
    #pragma unroll
    for (int o = 16; o; o >>= 1) m = fmaxf(m, __shfl_xor_sync(0xffffffffu, m, o));
    __shared__ float s[32];
    int w = threadIdx.x >> 5, l = threadIdx.x & 31;
    if (l == 0) s[w] = m;
    __syncthreads();
    if (w == 0) {
        m = (l < (blockDim.x >> 5)) ? s[l] : 0.f;
        #pragma unroll
        for (int o = 16; o; o >>= 1) m = fmaxf(m, __shfl_xor_sync(0xffffffffu, m, o));
        if (l == 0) atomicMax(&g_sx_bits, __float_as_uint(m));
    }
}

__global__ void k_absmax_w(const float* __restrict__ w1, const float* __restrict__ w2) {
    const float* w = blockIdx.x ? w2 : w1;
    float m = 0.f;
    for (int i = threadIdx.x; i < CC*CC*9; i += blockDim.x) m = fmaxf(m, fabsf(w[i]));
    #pragma unroll
    for (int o = 16; o; o >>= 1) m = fmaxf(m, __shfl_xor_sync(0xffffffffu, m, o));
    __shared__ float s[32];
    int wi = threadIdx.x >> 5, l = threadIdx.x & 31;
    if (l == 0) s[wi] = m;
    __syncthreads();
    if (wi == 0) {
        m = (l < (blockDim.x >> 5)) ? s[l] : 0.f;
        #pragma unroll
        for (int o = 16; o; o >>= 1) m = fmaxf(m, __shfl_xor_sync(0xffffffffu, m, o));
        if (l == 0) { float sc = m + 1e-12f; if (blockIdx.x) g_sw2 = sc; else g_sw1 = sc; }
    }
}

// NCHW fp32 -> int8 into PADDED NHWC (zero ring untouched)
__global__ void k_quant_x(const float* __restrict__ x) {
    __shared__ signed char t8[CC][120];
    int n = blockIdx.y, hw0 = blockIdx.x * 112;
    float qs = 127.f / (__uint_as_float(g_sx_bits) + 1e-12f);
    for (int i = threadIdx.x; i < CC*112; i += blockDim.x) {
        int c = i / 112, p = i % 112;
        float v = x[(size_t)(n*CC + c)*HWS + hw0 + p];
        int qi = __float2int_rn(v * qs);
        qi = max(-127, min(127, qi));
        t8[c][p] = (signed char)qi;
    }
    __syncthreads();
    signed char* abase = g_apad + (size_t)GUARD*CC;
    for (int i = threadIdx.x; i < 112*32; i += blockDim.x) {
        int p = i / 32, cq = i % 32;
        char4 v = make_char4(t8[cq*4][p], t8[cq*4+1][p], t8[cq*4+2][p], t8[cq*4+3][p]);
        int lidx = hw0 + p, h = lidx / WW, w = lidx % WW;
        *reinterpret_cast<char4*>(abase + ((size_t)n*PIMG + (h+1)*HP + (w+1))*CC + cq*4) = v;
    }
}

// OIHW fp32 -> [tap][co][ci] int8
__global__ void k_quant_w(const float* __restrict__ w1, const float* __restrict__ w2) {
    int t = blockIdx.y;
    const float* w = t ? w2 : w1;
    signed char* o = t ? g_w2q : g_w1q;
    float q = 127.f / (t ? g_sw2 : g_sw1);
    for (int i = blockIdx.x*blockDim.x + threadIdx.x; i < CC*9*CC; i += gridDim.x*blockDim.x) {
        int co = i / (9*CC), r = i % (9*CC), tap = r / CC, ci = r % CC;
        float v = w[(co*CC + ci)*9 + tap];
        int qi = __float2int_rn(v * q);
        qi = max(-127, min(127, qi));
        o[((size_t)tap*CC + co)*CC + ci] = (signed char)qi;
    }
}

// copy one tap's A + B tiles to smem with XOR-16B swizzle (cp.async)
__device__ __forceinline__ void prefetch_tap(const signed char* abase, const signed char* wl,
                                             int tap, uint32_t smA, uint32_t smB, int tid) {
    int tapoff = ((tap/3) - 1)*HP + (tap%3) - 1;
    const char* asrc = (const char*)abase + (ptrdiff_t)tapoff * CC;
    #pragma unroll
    for (int i = tid; i < 1024; i += 256) {
        int row = i >> 3, c = i & 7;
        cpasync16(smA + row*128 + ((c ^ (row & 7)) << 4), asrc + row*128 + c*16);
    }
    const char* bsrc = (const char*)wl + (size_t)tap*TAPB;
    #pragma unroll
    for (int i = tid; i < 1024; i += 256) {
        int row = i >> 3, c = i & 7;
        cpasync16(smB + row*128 + ((c ^ (row & 7)) << 4), bsrc + row*128 + c*16);
    }
    CP_COMMIT();
}

// implicit-GEMM 3x3 conv via int8 mma.sync: CTA = 128 padded pixels x 128 co
__global__ void __launch_bounds__(256, 1) k_conv(int layer) {
    extern __shared__ char sm[];
    uint32_t smb = smem_u32(sm);

    int tid = threadIdx.x, lane = tid & 31, wid = tid >> 5;
    int img = blockIdx.x / NTILE, tile = blockIdx.x % NTILE;
    int warpM = wid & 3, warpN = wid >> 2;

    const signed char* abase = g_apad + (size_t)GUARD*CC + ((size_t)img*PIMG + tile*128)*CC;
    const signed char* wl = layer ? g_w2q : g_w1q;

    int acc[2][8][4] = {};

    prefetch_tap(abase, wl, 0, smb, smb + TAPB, tid);

    int rowA0 = warpM*32 + (lane & 15);
    int rowB0 = warpN*64 + (lane & 7) + ((lane >> 4) << 3);
    int chA_add = lane >> 4;        // +0/+1 16B chunk
    int chB_add = (lane >> 3) & 1;

    for (int t = 0; t < 9; t++) {
        __syncthreads();
        if (t < 8) {
            uint32_t s = smb + ((t+1) & 1)*2*TAPB;
            prefetch_tap(abase, wl, t+1, s, s + TAPB, tid);
            CP_WAIT1();
        } else {
            CP_WAIT0();
        }
        __syncthreads();

        uint32_t smA = smb + (t & 1)*2*TAPB;
        uint32_t smB = smA + TAPB;

        #pragma unroll
        for (int ks = 0; ks < 4; ks++) {
            uint32_t a[2][4];
            #pragma unroll
            for (int mf = 0; mf < 2; mf++) {
                int r = rowA0 + mf*16;
                int ch = 2*ks + chA_add;
                ldsm_x4(a[mf][0], a[mf][1], a[mf][2], a[mf][3],
                        smA + r*128 + ((ch ^ (r & 7)) << 4));
            }
            uint32_t b[8][2];
            #pragma unroll
            for (int nf2 = 0; nf2 < 4; nf2++) {
                int r = rowB0 + nf2*16;
                int ch = 2*ks + chB_add;
                uint32_t b0, b1, b2, b3;
                ldsm_x4(b0, b1, b2, b3, smB + r*128 + ((ch ^ (r & 7)) << 4));
                b[nf2*2][0] = b0; b[nf2*2][1] = b1;
                b[nf2*2+1][0] = b2; b[nf2*2+1][1] = b3;
            }
            #pragma unroll
            for (int mf = 0; mf < 2; mf++)
                #pragma unroll
                for (int nf = 0; nf < 8; nf++)
                    mma_s8(acc[mf][nf], a[mf], b[nf]);
        }
    }

    float sact  = layer ? g_sa1 : (__uint_as_float(g_sx_bits) + 1e-12f);
    float sw    = layer ? g_sw2 : g_sw1;
    float scale = sact * sw * (1.f/16129.f);

    #pragma unroll
    for (int mf = 0; mf < 2; mf++) {
        int rl = warpM*32 + mf*16 + (lane >> 2);
        #pragma unroll
        for (int half = 0; half < 2; half++) {
            int pixl = tile*128 + rl + half*8;
            int hp = pixl / HP, wp = pixl % HP;
            if (hp >= 1 && hp <= HH && wp >= 1 && wp <= WW) {
                float* dst = g_y + ((size_t)img*HWS + (hp-1)*WW + (wp-1))*CC;
                #pragma unroll
                for (int nf = 0; nf < 8; nf++) {
                    int col = warpN*64 + nf*8 + (lane & 3)*2;
                    float2 v;
                    v.x = (float)acc[mf][nf][half*2+0] * scale;
                    v.y = (float)acc[mf][nf][half*2+1] * scale;
                    *reinterpret_cast<float2*>(dst + col) = v;
                }
            }
        }
    }
}

// deterministic per-block partial BN stats over compact NHWC g_y
__global__ void k_bnstats() {
    int tid = threadIdx.x;
    int c = tid & 127, half = tid >> 7;
    double s = 0.0, s2 = 0.0;
    float mn = 3.4e38f, mx = -3.4e38f;
    for (int pix = blockIdx.x*2 + half; pix < NPIX; pix += gridDim.x*2) {
        float v = g_y[(size_t)pix*CC + c];
        s += (double)v;
        s2 = fma((double)v, (double)v, s2);
        mn = fminf(mn, v); mx = fmaxf(mx, v);
    }
    __shared__ double ss[CC], ss2[CC];
    __shared__ float  smn[CC], smx[CC];
    if (half) { ss[c] = s; ss2[c] = s2; smn[c] = mn; smx[c] = mx; }
    __syncthreads();
    if (!half) {
        s += ss[c]; s2 += ss2[c];
        mn = fminf(mn, smn[c]); mx = fmaxf(mx, smx[c]);
        int o = blockIdx.x*CC + c;
        g_psum[o] = s; g_psum2[o] = s2; g_pmin[o] = mn; g_pmax[o] = mx;
    }
}

__global__ void k_bnfin(const float* __restrict__ gamma, const float* __restrict__ beta,
                        int layer, int doAct) {
    int tid = threadIdx.x;
    int c = tid & 127, q = tid >> 7;
    double s = 0.0, s2 = 0.0;
    float mn = 3.4e38f, mx = -3.4e38f;
    for (int b = q; b < SBLK; b += 4) {
        int o = b*CC + c;
        s += g_psum[o]; s2 += g_psum2[o];
        mn = fminf(mn, g_pmin[o]); mx = fmaxf(mx, g_pmax[o]);
    }
    __shared__ double ss[512], ss2[512];
    __shared__ float  smn[512], smx[512];
    __shared__ float  actmax[CC];
    ss[tid] = s; ss2[tid] = s2; smn[tid] = mn; smx[tid] = mx;
    __syncthreads();
    if (q == 0) {
        #pragma unroll
        for (int k = 1; k < 4; k++) {
            s += ss[k*128 + c]; s2 += ss2[k*128 + c];
            mn = fminf(mn, smn[k*128 + c]); mx = fmaxf(mx, smx[k*128 + c]);
        }
        double mean = s / (double)NPIX;
        double var  = s2 / (double)NPIX - mean*mean;
        float rstd = (float)(1.0 / sqrt(var + 1e-5));
        float A  = gamma[c] * rstd;
        float Bc = beta[c] - (float)mean * A;
        g_bnA[layer*CC + c] = A;
        g_bnB[layer*CC + c] = Bc;
        actmax[c] = fmaxf(fmaxf(mx*A + Bc, 0.f), fmaxf(mn*A + Bc, 0.f));
    }
    __syncthreads();
    if (doAct && tid == 0) {
        float m = 0.f;
        for (int k = 0; k < CC; k++) m = fmaxf(m, actmax[k]);
        g_sa1 = m + 1e-12f;
    }
}

// bn1 + relu + quantize -> padded int8 activations for layer 2
__global__ void k_bnq() {
    int i4 = blockIdx.x*blockDim.x + threadIdx.x;
    if (i4 >= NELT/4) return;
    float qa = 127.f / g_sa1;
    float4 v = reinterpret_cast<const float4*>(g_y)[i4];
    int p = i4 >> 5, cb = (i4 & 31)*4;
    float t0 = fmaxf(v.x*g_bnA[cb+0] + g_bnB[cb+0], 0.f);
    float t1 = fmaxf(v.y*g_bnA[cb+1] + g_bnB[cb+1], 0.f);
    float t2 = fmaxf(v.z*g_bnA[cb+2] + g_bnB[cb+2], 0.f);
    float t3 = fmaxf(v.w*g_bnA[cb+3] + g_bnB[cb+3], 0.f);
    char4 o;
    o.x = (signed char)max(-127, min(127, __float2int_rn(t0*qa)));
    o.y = (signed char)max(-127, min(127, __float2int_rn(t1*qa)));
    o.z = (signed char)max(-127, min(127, __float2int_rn(t2*qa)));
    o.w = (signed char)max(-127, min(127, __float2int_rn(t3*qa)));
    int n = p / HWS, r = p % HWS, h = r / WW, w = r % WW;
    signed char* abase = g_apad + (size_t)GUARD*CC;
    *reinterpret_cast<char4*>(abase + ((size_t)n*PIMG + (h+1)*HP + (w+1))*CC + cb) = o;
}

// bn2 + identity add + relu, NHWC -> NCHW via smem transpose
__global__ void k_final(const float* __restrict__ x, float* __restrict__ out) {
    __shared__ float t[CC][57];
    int n = blockIdx.y, row = blockIdx.x;
    int hw0 = row * WW;
    for (int i = threadIdx.x; i < WW*CC; i += blockDim.x) {
        int c = i & 127, p = i >> 7;
        t[c][p] = g_y[(size_t)(n*HWS + hw0 + p)*CC + c];
    }
    __syncthreads();
    for (int i = threadIdx.x; i < CC*WW; i += blockDim.x) {
        int c = i / WW, p = i % WW;
        size_t gi = (size_t)(n*CC + c)*HWS + hw0 + p;
        float v = t[c][p]*g_bnA[CC + c] + g_bnB[CC + c] + x[gi];
        out[gi] = fmaxf(v, 0.f);
    }
}

// ---------------------------------------------------------------- launcher --
extern "C" void kernel_launch(void* const* d_in, const int* in_sizes, int n_in,
                              void* d_out, int out_size) {
    const float* x      = (const float*)d_in[0];
    const float* w1     = (const float*)d_in[1];
    const float* gamma1 = (const float*)d_in[2];
    const float* beta1  = (const float*)d_in[3];
    const float* w2     = (const float*)d_in[4];
    const float* gamma2 = (const float*)d_in[5];
    const float* beta2  = (const float*)d_in[6];
    float* out = (float*)d_out;
    (void)in_sizes; (void)n_in; (void)out_size;

    cudaFuncSetAttribute(k_conv, cudaFuncAttributeMaxDynamicSharedMemorySize, CONV_SMEM);

    k_zero<<<1, 1>>>();
    k_absmax_x<<<1024, 256>>>(x);
    k_absmax_w<<<2, 1024>>>(w1, w2);
    k_quant_x<<<dim3(28, BB), 256>>>(x);
    k_quant_w<<<dim3(64, 2), 256>>>(w1, w2);

    k_conv<<<BB*NTILE, 256, CONV_SMEM>>>(0);
    k_bnstats<<<SBLK, 256>>>();
    k_bnfin<<<1, 512>>>(gamma1, beta1, 0, 1);
    k_bnq<<<(NELT/4 + 255)/256, 256>>>();

    k_conv<<<BB*NTILE, 256, CONV_SMEM>>>(1);
    k_bnstats<<<SBLK, 256>>>();
    k_bnfin<<<1, 512>>>(gamma2, beta2, 1, 0);
    k_final<<<dim3(HH, BB), 256>>>(x, out);
}

// round 8
// speedup vs baseline: 1.4620x; 1.3945x over previous
#include <cuda_runtime.h>
#include <cuda_bf16.h>
#include <cstdint>

#define BB   32
#define CC   128
#define HH   56
#define WW   56
#define HWS  (HH*WW)          // 3136
#define NPIX (BB*HWS)         // 100352
#define NELT (NPIX*CC)        // 12845056
#define SBLK 1024

// padded spatial layout: 58x58 per image (zero ring) + guard rows front/back
#define HP    58
#define PIMG  (HP*HP)         // 3364
#define GUARD 192             // guard rows (128 ch each) for tap shifts / tile overflow
#define NTILE 27              // ceil(3364/128)
#define TAPB  32768           // one 128(pix|co) x 128(ci) bf16 tile
#define CONV_SMEM (4*TAPB)    // 2 stages x (A+B) = 128KB

// ----------------------------- scratch (device globals: no runtime allocs) --
__device__ __nv_bfloat16 g_apad[((size_t)GUARD + (size_t)BB*PIMG + GUARD) * CC]; // padded acts bf16
__device__ float         g_y[NELT];           // conv output, compact NHWC fp32
__device__ __nv_bfloat16 g_w1q[9*CC*CC];      // [tap][co][ci] bf16 (quantized ints)
__device__ __nv_bfloat16 g_w2q[9*CC*CC];
__device__ unsigned      g_sx_bits;
__device__ float         g_sw1, g_sw2, g_sa1;
__device__ float         g_bnA[2*CC], g_bnB[2*CC];
__device__ double        g_psum[SBLK*CC], g_psum2[SBLK*CC];
__device__ float         g_pmin[SBLK*CC], g_pmax[SBLK*CC];

// --------------------------------------------------------------- PTX glue --
__device__ __forceinline__ uint32_t smem_u32(const void* p) {
    uint32_t a;
    asm("{ .reg .u64 t; cvta.to.shared.u64 t, %1; cvt.u32.u64 %0, t; }" : "=r"(a) : "l"(p));
    return a;
}
__device__ __forceinline__ void cpasync16(uint32_t dst, const void* src) {
    asm volatile("cp.async.cg.shared.global [%0], [%1], 16;" :: "r"(dst), "l"(src));
}
#define CP_COMMIT() asm volatile("cp.async.commit_group;" ::: "memory")
#define CP_WAIT0()  asm volatile("cp.async.wait_group 0;" ::: "memory")
#define CP_WAIT1()  asm volatile("cp.async.wait_group 1;" ::: "memory")

__device__ __forceinline__ void ldsm_x4(uint32_t& r0, uint32_t& r1, uint32_t& r2, uint32_t& r3,
                                        uint32_t addr) {
    asm volatile("ldmatrix.sync.aligned.m8n8.x4.shared.b16 {%0,%1,%2,%3}, [%4];"
                 : "=r"(r0), "=r"(r1), "=r"(r2), "=r"(r3) : "r"(addr));
}
__device__ __forceinline__ void mma_bf16(float* c, const uint32_t* a, const uint32_t* b) {
    asm volatile("mma.sync.aligned.m16n8k16.row.col.f32.bf16.bf16.f32 "
                 "{%0,%1,%2,%3}, {%4,%5,%6,%7}, {%8,%9}, {%0,%1,%2,%3};"
                 : "+f"(c[0]), "+f"(c[1]), "+f"(c[2]), "+f"(c[3])
                 : "r"(a[0]), "r"(a[1]), "r"(a[2]), "r"(a[3]), "r"(b[0]), "r"(b[1]));
}

// ----------------------------------------------------------------- helpers --
__global__ void k_zero() { g_sx_bits = 0u; }

__global__ void k_absmax_x(const float* __restrict__ x) {
    float m = 0.f;
    for (int i = blockIdx.x*blockDim.x + threadIdx.x; i < NELT; i += gridDim.x*blockDim.x)
        m = fmaxf(m, fabsf(x[i]));
    #pragma unroll
    for (int o = 16; o; o >>= 1) m = fmaxf(m, __shfl_xor_sync(0xffffffffu, m, o));
    __shared__ float s[32];
    int w = threadIdx.x >> 5, l = threadIdx.x & 31;
    if (l == 0) s[w] = m;
    __syncthreads();
    if (w == 0) {
        m = (l < (blockDim.x >> 5)) ? s[l] : 0.f;
        #pragma unroll
        for (int o = 16; o; o >>= 1) m = fmaxf(m, __shfl_xor_sync(0xffffffffu, m, o));
        if (l == 0) atomicMax(&g_sx_bits, __float_as_uint(m));
    }
}

__global__ void k_absmax_w(const float* __restrict__ w1, const float* __restrict__ w2) {
    const float* w = blockIdx.x ? w2 : w1;
    float m = 0.f;
    for (int i = threadIdx.x; i < CC*CC*9; i += blockDim.x) m = fmaxf(m, fabsf(w[i]));
    #pragma unroll
    for (int o = 16; o; o >>= 1) m = fmaxf(m, __shfl_xor_sync(0xffffffffu, m, o));
    __shared__ float s[32];
    int wi = threadIdx.x >> 5, l = threadIdx.x & 31;
    if (l == 0) s[wi] = m;
    __syncthreads();
    if (wi == 0) {
        m = (l < (blockDim.x >> 5)) ? s[l] : 0.f;
        #pragma unroll
        for (int o = 16; o; o >>= 1) m = fmaxf(m, __shfl_xor_sync(0xffffffffu, m, o));
        if (l == 0) { float sc = m + 1e-12f; if (blockIdx.x) g_sw2 = sc; else g_sw1 = sc; }
    }
}

// NCHW fp32 -> quantized bf16 into PADDED NHWC (zero ring untouched)
__global__ void k_quant_x(const float* __restrict__ x) {
    __shared__ __nv_bfloat16 t[CC][121];
    int n = blockIdx.y, hw0 = blockIdx.x * 112;
    float qs = 127.f / (__uint_as_float(g_sx_bits) + 1e-12f);
    for (int i = threadIdx.x; i < CC*112; i += blockDim.x) {
        int c = i / 112, p = i % 112;
        float v = x[(size_t)(n*CC + c)*HWS + hw0 + p];
        int qi = __float2int_rn(v * qs);
        qi = max(-127, min(127, qi));
        t[c][p] = __float2bfloat16_rn((float)qi);   // exact for |qi|<=127
    }
    __syncthreads();
    __nv_bfloat16* abase = g_apad + (size_t)GUARD*CC;
    for (int i = threadIdx.x; i < 112*64; i += blockDim.x) {
        int p = i / 64, cq = i % 64;
        int lidx = hw0 + p, h = lidx / WW, w = lidx % WW;
        __nv_bfloat162 v2; v2.x = t[2*cq][p]; v2.y = t[2*cq+1][p];
        *reinterpret_cast<__nv_bfloat162*>(
            abase + ((size_t)n*PIMG + (h+1)*HP + (w+1))*CC + 2*cq) = v2;
    }
}

// OIHW fp32 -> [tap][co][ci] quantized bf16
__global__ void k_quant_w(const float* __restrict__ w1, const float* __restrict__ w2) {
    int t = blockIdx.y;
    const float* w = t ? w2 : w1;
    __nv_bfloat16* o = t ? g_w2q : g_w1q;
    float q = 127.f / (t ? g_sw2 : g_sw1);
    for (int i = blockIdx.x*blockDim.x + threadIdx.x; i < CC*9*CC; i += gridDim.x*blockDim.x) {
        int co = i / (9*CC), r = i % (9*CC), tap = r / CC, ci = r % CC;
        float v = w[(co*CC + ci)*9 + tap];
        int qi = __float2int_rn(v * q);
        qi = max(-127, min(127, qi));
        o[((size_t)tap*CC + co)*CC + ci] = __float2bfloat16_rn((float)qi);
    }
}

// copy one tap's A + B bf16 tiles to smem with XOR-16B swizzle (cp.async)
// rows are 256B (=16 chunks of 16B); swizzle chunk c -> c ^ (row & 7)
__device__ __forceinline__ void prefetch_tap(const __nv_bfloat16* abase, const __nv_bfloat16* wl,
                                             int tap, uint32_t smA, uint32_t smB, int tid) {
    int tapoff = ((tap/3) - 1)*HP + (tap%3) - 1;
    const char* asrc = (const char*)(abase + (ptrdiff_t)tapoff * CC);
    #pragma unroll
    for (int i = tid; i < 2048; i += 256) {
        int row = i >> 4, c = i & 15;
        cpasync16(smA + row*256 + ((c ^ (row & 7)) << 4), asrc + row*256 + c*16);
    }
    const char* bsrc = (const char*)(wl + (size_t)tap*CC*CC);
    #pragma unroll
    for (int i = tid; i < 2048; i += 256) {
        int row = i >> 4, c = i & 15;
        cpasync16(smB + row*256 + ((c ^ (row & 7)) << 4), bsrc + row*256 + c*16);
    }
    CP_COMMIT();
}

// implicit-GEMM 3x3 conv via bf16 HMMA mma.sync: CTA = 128 padded pixels x 128 co
__global__ void __launch_bounds__(256, 1) k_conv(int layer) {
    extern __shared__ char sm[];
    uint32_t smb = smem_u32(sm);

    int tid = threadIdx.x, lane = tid & 31, wid = tid >> 5;
    int img = blockIdx.x / NTILE, tile = blockIdx.x % NTILE;
    int warpM = wid & 3, warpN = wid >> 2;

    const __nv_bfloat16* abase = g_apad + (size_t)GUARD*CC + ((size_t)img*PIMG + tile*128)*CC;
    const __nv_bfloat16* wl = layer ? g_w2q : g_w1q;

    float acc[2][8][4] = {};

    prefetch_tap(abase, wl, 0, smb, smb + TAPB, tid);

    int rowA0 = warpM*32 + (lane & 15);
    int rowB0 = warpN*64 + (lane & 7) + ((lane >> 4) << 3);
    int chA_add = lane >> 4;        // +0/+1 16B chunk within k-step
    int chB_add = (lane >> 3) & 1;

    for (int t = 0; t < 9; t++) {
        __syncthreads();
        if (t < 8) {
            uint32_t s = smb + ((t+1) & 1)*2*TAPB;
            prefetch_tap(abase, wl, t+1, s, s + TAPB, tid);
            CP_WAIT1();
        } else {
            CP_WAIT0();
        }
        __syncthreads();

        uint32_t smA = smb + (t & 1)*2*TAPB;
        uint32_t smB = smA + TAPB;

        #pragma unroll
        for (int ks = 0; ks < 8; ks++) {         // K=16 bf16 per step
            uint32_t a[2][4];
            #pragma unroll
            for (int mf = 0; mf < 2; mf++) {
                int r = rowA0 + mf*16;
                int ch = 2*ks + chA_add;
                ldsm_x4(a[mf][0], a[mf][1], a[mf][2], a[mf][3],
                        smA + r*256 + ((ch ^ (r & 7)) << 4));
            }
            uint32_t b[8][2];
            #pragma unroll
            for (int nf2 = 0; nf2 < 4; nf2++) {
                int r = rowB0 + nf2*16;
                int ch = 2*ks + chB_add;
                uint32_t b0, b1, b2, b3;
                ldsm_x4(b0, b1, b2, b3, smB + r*256 + ((ch ^ (r & 7)) << 4));
                b[nf2*2][0] = b0; b[nf2*2][1] = b1;
                b[nf2*2+1][0] = b2; b[nf2*2+1][1] = b3;
            }
            #pragma unroll
            for (int mf = 0; mf < 2; mf++)
                #pragma unroll
                for (int nf = 0; nf < 8; nf++)
                    mma_bf16(acc[mf][nf], a[mf], b[nf]);
        }
    }

    float sact  = layer ? g_sa1 : (__uint_as_float(g_sx_bits) + 1e-12f);
    float sw    = layer ? g_sw2 : g_sw1;
    float scale = sact * sw * (1.f/16129.f);

    #pragma unroll
    for (int mf = 0; mf < 2; mf++) {
        int rl = warpM*32 + mf*16 + (lane >> 2);
        #pragma unroll
        for (int half = 0; half < 2; half++) {
            int pixl = tile*128 + rl + half*8;
            int hp = pixl / HP, wp = pixl % HP;
            if (hp >= 1 && hp <= HH && wp >= 1 && wp <= WW) {
                float* dst = g_y + ((size_t)img*HWS + (hp-1)*WW + (wp-1))*CC;
                #pragma unroll
                for (int nf = 0; nf < 8; nf++) {
                    int col = warpN*64 + nf*8 + (lane & 3)*2;
                    float2 v;
                    v.x = acc[mf][nf][half*2+0] * scale;
                    v.y = acc[mf][nf][half*2+1] * scale;
                    *reinterpret_cast<float2*>(dst + col) = v;
                }
            }
        }
    }
}

// deterministic per-block partial BN stats over compact NHWC g_y
__global__ void k_bnstats() {
    int tid = threadIdx.x;
    int c = tid & 127, half = tid >> 7;
    double s = 0.0, s2 = 0.0;
    float mn = 3.4e38f, mx = -3.4e38f;
    for (int pix = blockIdx.x*2 + half; pix < NPIX; pix += gridDim.x*2) {
        float v = g_y[(size_t)pix*CC + c];
        s += (double)v;
        s2 = fma((double)v, (double)v, s2);
        mn = fminf(mn, v); mx = fmaxf(mx, v);
    }
    __shared__ double ss[CC], ss2[CC];
    __shared__ float  smn[CC], smx[CC];
    if (half) { ss[c] = s; ss2[c] = s2; smn[c] = mn; smx[c] = mx; }
    __syncthreads();
    if (!half) {
        s += ss[c]; s2 += ss2[c];
        mn = fminf(mn, smn[c]); mx = fmaxf(mx, smx[c]);
        int o = blockIdx.x*CC + c;
        g_psum[o] = s; g_psum2[o] = s2; g_pmin[o] = mn; g_pmax[o] = mx;
    }
}

__global__ void k_bnfin(const float* __restrict__ gamma, const float* __restrict__ beta,
                        int layer, int doAct) {
    int tid = threadIdx.x;
    int c = tid & 127, q = tid >> 7;
    double s = 0.0, s2 = 0.0;
    float mn = 3.4e38f, mx = -3.4e38f;
    for (int b = q; b < SBLK; b += 4) {
        int o = b*CC + c;
        s += g_psum[o]; s2 += g_psum2[o];
        mn = fminf(mn, g_pmin[o]); mx = fmaxf(mx, g_pmax[o]);
    }
    __shared__ double ss[512], ss2[512];
    __shared__ float  smn[512], smx[512];
    __shared__ float  actmax[CC];
    ss[tid] = s; ss2[tid] = s2; smn[tid] = mn; smx[tid] = mx;
    __syncthreads();
    if (q == 0) {
        #pragma unroll
        for (int k = 1; k < 4; k++) {
            s += ss[k*128 + c]; s2 += ss2[k*128 + c];
            mn = fminf(mn, smn[k*128 + c]); mx = fmaxf(mx, smx[k*128 + c]);
        }
        double mean = s / (double)NPIX;
        double var  = s2 / (double)NPIX - mean*mean;
        float rstd = (float)(1.0 / sqrt(var + 1e-5));
        float A  = gamma[c] * rstd;
        float Bc = beta[c] - (float)mean * A;
        g_bnA[layer*CC + c] = A;
        g_bnB[layer*CC + c] = Bc;
        actmax[c] = fmaxf(fmaxf(mx*A + Bc, 0.f), fmaxf(mn*A + Bc, 0.f));
    }
    __syncthreads();
    if (doAct && tid == 0) {
        float m = 0.f;
        for (int k = 0; k < CC; k++) m = fmaxf(m, actmax[k]);
        g_sa1 = m + 1e-12f;
    }
}

// bn1 + relu + quantize -> padded bf16 activations for layer 2
__global__ void k_bnq() {
    int i4 = blockIdx.x*blockDim.x + threadIdx.x;
    if (i4 >= NELT/4) return;
    float qa = 127.f / g_sa1;
    float4 v = reinterpret_cast<const float4*>(g_y)[i4];
    int p = i4 >> 5, cb = (i4 & 31)*4;
    float t0 = fmaxf(v.x*g_bnA[cb+0] + g_bnB[cb+0], 0.f);
    float t1 = fmaxf(v.y*g_bnA[cb+1] + g_bnB[cb+1], 0.f);
    float t2 = fmaxf(v.z*g_bnA[cb+2] + g_bnB[cb+2], 0.f);
    float t3 = fmaxf(v.w*g_bnA[cb+3] + g_bnB[cb+3], 0.f);
    int q0 = max(-127, min(127, __float2int_rn(t0*qa)));
    int q1 = max(-127, min(127, __float2int_rn(t1*qa)));
    int q2 = max(-127, min(127, __float2int_rn(t2*qa)));
    int q3 = max(-127, min(127, __float2int_rn(t3*qa)));
    int n = p / HWS, r = p % HWS, h = r / WW, w = r % WW;
    __nv_bfloat16* abase = g_apad + (size_t)GUARD*CC;
    __nv_bfloat162 lo, hi;
    lo.x = __float2bfloat16_rn((float)q0); lo.y = __float2bfloat16_rn((float)q1);
    hi.x = __float2bfloat16_rn((float)q2); hi.y = __float2bfloat16_rn((float)q3);
    uint2 pk;
    pk.x = *reinterpret_cast<uint32_t*>(&lo);
    pk.y = *reinterpret_cast<uint32_t*>(&hi);
    *reinterpret_cast<uint2*>(abase + ((size_t)n*PIMG + (h+1)*HP + (w+1))*CC + cb) = pk;
}

// bn2 + identity add + relu, NHWC -> NCHW via smem transpose
__global__ void k_final(const float* __restrict__ x, float* __restrict__ out) {
    __shared__ float t[CC][57];
    int n = blockIdx.y, row = blockIdx.x;
    int hw0 = row * WW;
    for (int i = threadIdx.x; i < WW*CC; i += blockDim.x) {
        int c = i & 127, p = i >> 7;
        t[c][p] = g_y[(size_t)(n*HWS + hw0 + p)*CC + c];
    }
    __syncthreads();
    for (int i = threadIdx.x; i < CC*WW; i += blockDim.x) {
        int c = i / WW, p = i % WW;
        size_t gi = (size_t)(n*CC + c)*HWS + hw0 + p;
        float v = t[c][p]*g_bnA[CC + c] + g_bnB[CC + c] + x[gi];
        out[gi] = fmaxf(v, 0.f);
    }
}

// ---------------------------------------------------------------- launcher --
extern "C" void kernel_launch(void* const* d_in, const int* in_sizes, int n_in,
                              void* d_out, int out_size) {
    const float* x      = (const float*)d_in[0];
    const float* w1     = (const float*)d_in[1];
    const float* gamma1 = (const float*)d_in[2];
    const float* beta1  = (const float*)d_in[3];
    const float* w2     = (const float*)d_in[4];
    const float* gamma2 = (const float*)d_in[5];
    const float* beta2  = (const float*)d_in[6];
    float* out = (float*)d_out;
    (void)in_sizes; (void)n_in; (void)out_size;

    cudaFuncSetAttribute(k_conv, cudaFuncAttributeMaxDynamicSharedMemorySize, CONV_SMEM);

    k_zero<<<1, 1>>>();
    k_absmax_x<<<1024, 256>>>(x);
    k_absmax_w<<<2, 1024>>>(w1, w2);
    k_quant_x<<<dim3(28, BB), 256>>>(x);
    k_quant_w<<<dim3(64, 2), 256>>>(w1, w2);

    k_conv<<<BB*NTILE, 256, CONV_SMEM>>>(0);
    k_bnstats<<<SBLK, 256>>>();
    k_bnfin<<<1, 512>>>(gamma1, beta1, 0, 1);
    k_bnq<<<(NELT/4 + 255)/256, 256>>>();

    k_conv<<<BB*NTILE, 256, CONV_SMEM>>>(1);
    k_bnstats<<<SBLK, 256>>>();
    k_bnfin<<<1, 512>>>(gamma2, beta2, 1, 0);
    k_final<<<dim3(HH, BB), 256>>>(x, out);
}